// round 6
// baseline (speedup 1.0000x reference)
#include <cuda_runtime.h>
#include <cstdint>
#include <cstddef>

// Problem constants
#define BB    32
#define TT    2048
#define FIN   63
#define FDIM  64
#define LUDIM 640
#define NCH   64      // t-chunks for the parallel scan
#define TC    32      // timesteps per chunk
#define NCHAIN 2048   // B*U chains

// GEMM tiling (round-3 proven config)
#define BT   128      // t rows per block
#define BLU  128      // lu cols per block
#define TPAD 132      // padded t stride for f-major X tile

// Scratch. P stored TRANSPOSED: P_T[b][lu][t]  (lu = l*64+u) -> scan reads
// become contiguous per-thread streams (one 128B line per l per chunk).
__device__ float g_PT[(size_t)BB * LUDIM * TT];     // 167.8 MB
__device__ float g_W[(size_t)NCH * 17 * NCHAIN];    // 8.9 MB

// ---------------- f32x2 helpers (Blackwell packed fp32) ----------------
__device__ __forceinline__ void ffma2(unsigned long long &a, unsigned long long x, unsigned long long k) {
    asm("fma.rn.f32x2 %0, %1, %2, %0;" : "+l"(a) : "l"(x), "l"(k));
}
__device__ __forceinline__ float2 unpack2(unsigned long long v) {
    float2 r;
    asm("mov.b64 {%0,%1}, %2;" : "=f"(r.x), "=f"(r.y) : "l"(v));
    return r;
}

// ---------------- Kernel 1: P_T = (X @ K)^T  (X = [x | time]) ----------------
// ROUND-3 CORE (141.5us, best known): 256 thr, 8t x 8lu per thread, t-pair
// f32x2 lanes, dup-K conflict-free LDS. NEW: transposed epilogue — each
// thread's 8 consecutive t values per lu column store as 2x STG.128 (32B
// contiguous along t) into P_T[b][lu][t].
extern "C" __global__ void __launch_bounds__(256, 2)
lrsig_gemm(const float* __restrict__ x, const float* __restrict__ kern)
{
    extern __shared__ float smem[];
    float*  sX  = smem;                           // [f][TPAD] floats (f-major)
    float2* sKd = (float2*)(smem + FDIM * TPAD);  // [f][BLU] duplicated (k,k)

    const int tid = threadIdx.x;
    const int tx  = tid & 15;
    const int ty  = tid >> 4;
    const int t0  = blockIdx.x * BT;
    const int lu0 = blockIdx.y * BLU;
    const int b   = blockIdx.z;

    // Load X tile (gmem-coalesced over f), store f-major (transposed), padded.
    // f == 63 is the synthetic time feature: t*(2/(T-1)) - 1.
    for (int e = tid; e < BT * FDIM; e += 256) {
        int f  = e & 63;
        int tl = e >> 6;
        int t  = t0 + tl;
        float v;
        if (f < FIN) v = x[((size_t)b * TT + t) * FIN + f];
        else         v = (float)t * (2.0f / 2047.0f) - 1.0f;
        sX[f * TPAD + tl] = v;
    }
    // Load K tile duplicated: sKd[f*BLU + j] = (k, k), k = kern[f][lu0+j]
    for (int e = tid; e < FDIM * BLU; e += 256) {
        int f = e >> 7;
        int j = e & 127;
        float v = kern[f * LUDIM + lu0 + j];
        sKd[e] = make_float2(v, v);
    }
    __syncthreads();

    // acc[tp][c][k]: t-pair tp (t = t0 + ty*8 + 2*tp), col lu0 + 32*c + 2*tx + k
    unsigned long long acc[4][4][2];
#pragma unroll
    for (int tp = 0; tp < 4; tp++)
#pragma unroll
        for (int c = 0; c < 4; c++) { acc[tp][c][0] = 0ULL; acc[tp][c][1] = 0ULL; }

    const ulonglong2* Xu = reinterpret_cast<const ulonglong2*>(sX);   // 33 u2/row
    const ulonglong2* Kd = reinterpret_cast<const ulonglong2*>(sKd);  // 64 u2/row

#pragma unroll 8
    for (int f = 0; f < FDIM; f++) {
        // 8 t values = 4 packed (t,t+1) pairs; 2 broadcast LDS.128
        ulonglong2 xa = Xu[f * 33 + ty * 2];
        ulonglong2 xb = Xu[f * 33 + ty * 2 + 1];
        unsigned long long xp[4] = { xa.x, xa.y, xb.x, xb.y };
        // 4 conflict-free LDS.128 (16B stride across tx)
        ulonglong2 kc[4];
#pragma unroll
        for (int c = 0; c < 4; c++) kc[c] = Kd[f * 64 + c * 16 + tx];
#pragma unroll
        for (int tp = 0; tp < 4; tp++)
#pragma unroll
            for (int c = 0; c < 4; c++) {
                ffma2(acc[tp][c][0], xp[tp], kc[c].x);
                ffma2(acc[tp][c][1], xp[tp], kc[c].y);
            }
    }

    // Transposed epilogue: per owned column lu, this thread's 8 t values are
    // consecutive -> 2x float4 = 32B contiguous at P_T[b][lu][t0+ty*8].
    const int tbase = t0 + ty * 8;
#pragma unroll
    for (int c = 0; c < 4; c++)
#pragma unroll
        for (int k = 0; k < 2; k++) {
            float2 p0 = unpack2(acc[0][c][k]);
            float2 p1 = unpack2(acc[1][c][k]);
            float2 p2 = unpack2(acc[2][c][k]);
            float2 p3 = unpack2(acc[3][c][k]);
            int lu = lu0 + 32 * c + 2 * tx + k;
            float* op = g_PT + ((size_t)b * LUDIM + lu) * TT + tbase;
            reinterpret_cast<float4*>(op)[0] = make_float4(p0.x, p0.y, p1.x, p1.y);
            reinterpret_cast<float4*>(op)[1] = make_float4(p2.x, p2.y, p3.x, p3.y);
        }
}

// ---------------- Kernel 2: per-chunk scan coefficients ----------------
// One thread per (chain, chunk). Reads 10 contiguous t-streams from P_T
// (float4 loads; one full 128B line per l per chunk at TC=32).
extern "C" __global__ void __launch_bounds__(256)
lrsig_scan(void)
{
    const int c     = blockIdx.x;
    const int chain = blockIdx.y * 256 + threadIdx.x;
    const int b = chain >> 6;
    const int u = chain & 63;

    const float* base = g_PT + ((size_t)b * LUDIM + u) * TT;   // + l*64*TT + t
    const int t0 = c * TC;
    const int tp = (c == 0) ? 0 : (t0 - 1);

    float prev[10];
#pragma unroll
    for (int l = 0; l < 10; l++) prev[l] = base[(size_t)l * 64 * TT + tp];

    float e1=0.f,e3=0.f,e4=0.f,e43=0.f,e6=0.f,e7=0.f,e76=0.f,e8=0.f,e87=0.f,e876=0.f;
    float S2=0.f,S5=0.f,S9=0.f,W21=0.f,W54=0.f,W543=0.f,W98=0.f,W987=0.f,W9876=0.f,y0=0.f;

    for (int i4 = 0; i4 < TC / 4; i4++) {
        float4 q[10];
#pragma unroll
        for (int l = 0; l < 10; l++)
            q[l] = *reinterpret_cast<const float4*>(base + (size_t)l * 64 * TT + t0 + 4 * i4);
#pragma unroll
        for (int s = 0; s < 4; s++) {
            float m[10];
#pragma unroll
            for (int l = 0; l < 10; l++) {
                float v = (s == 0) ? q[l].x : (s == 1) ? q[l].y : (s == 2) ? q[l].z : q[l].w;
                m[l] = v - prev[l];
                prev[l] = v;
            }
            // All RHS use pre-update (exclusive) values.
            y0   += m[0];
            W21   = fmaf(m[2], e1,   W21);   S2 += m[2];
            W54   = fmaf(m[5], e4,   W54);
            W543  = fmaf(m[5], e43,  W543);  S5 += m[5];
            W98   = fmaf(m[9], e8,   W98);
            W987  = fmaf(m[9], e87,  W987);
            W9876 = fmaf(m[9], e876, W9876); S9 += m[9];
            e43   = fmaf(m[4], e3,   e43);
            e876  = fmaf(m[8], e76,  e876);
            e87   = fmaf(m[8], e7,   e87);
            e76   = fmaf(m[7], e6,   e76);
            e1 += m[1]; e3 += m[3]; e4 += m[4];
            e6 += m[6]; e7 += m[7]; e8 += m[8];
        }
    }

    float* w = g_W + (size_t)c * 17 * NCHAIN + chain;
    w[ 0 * NCHAIN] = y0 + W21 + W543 + W9876;  // state-independent Y contribution
    w[ 1 * NCHAIN] = S2;   w[ 2 * NCHAIN] = S5;   w[ 3 * NCHAIN] = S9;
    w[ 4 * NCHAIN] = W54;  w[ 5 * NCHAIN] = W98;  w[ 6 * NCHAIN] = W987;
    w[ 7 * NCHAIN] = e1;   w[ 8 * NCHAIN] = e3;   w[ 9 * NCHAIN] = e4;
    w[10 * NCHAIN] = e43;  w[11 * NCHAIN] = e6;   w[12 * NCHAIN] = e7;
    w[13 * NCHAIN] = e76;  w[14 * NCHAIN] = e8;   w[15 * NCHAIN] = e87;
    w[16 * NCHAIN] = e876;
}

// ---------------- Kernel 3: fold chunks per chain ----------------
extern "C" __global__ void __launch_bounds__(256)
lrsig_combine(float* __restrict__ out)
{
    const int chain = blockIdx.x * 256 + threadIdx.x;
    float y = 0.f, s1 = 0.f, s3 = 0.f, sa = 0.f, s6 = 0.f, sb = 0.f, sc = 0.f;

    for (int c = 0; c < NCH; c++) {
        const float* w = g_W + (size_t)c * 17 * NCHAIN + chain;
        float Y0   = w[ 0 * NCHAIN];
        float S2   = w[ 1 * NCHAIN], S5  = w[ 2 * NCHAIN], S9  = w[ 3 * NCHAIN];
        float W54  = w[ 4 * NCHAIN], W98 = w[ 5 * NCHAIN], W987= w[ 6 * NCHAIN];
        float E1   = w[ 7 * NCHAIN], E3  = w[ 8 * NCHAIN], E4  = w[ 9 * NCHAIN];
        float E43  = w[10 * NCHAIN], E6  = w[11 * NCHAIN], E7  = w[12 * NCHAIN];
        float E76  = w[13 * NCHAIN], E8  = w[14 * NCHAIN], E87 = w[15 * NCHAIN];
        float E876 = w[16 * NCHAIN];

        // Y contribution uses pre-chunk state
        y += Y0 + s1 * S2 + sa * S5 + s3 * W54 + sc * S9 + sb * W98 + s6 * W987;
        // State transition (sc/sb/sa use pre-update partners)
        sc += sb * E8 + s6 * E87 + E876;
        sb += s6 * E7 + E76;
        sa += s3 * E4 + E43;
        s1 += E1; s3 += E3; s6 += E6;
    }
    out[chain] = y;   // out[b*64 + u] == Y[b][u]
}

// ---------------- Launch ----------------
extern "C" void kernel_launch(void* const* d_in, const int* in_sizes, int n_in,
                              void* d_out, int out_size)
{
    const float* x    = (const float*)d_in[0];  // (32, 2048, 63) f32
    const float* kern = (const float*)d_in[1];  // (64, 10, 64)  f32

    const size_t smem_bytes = (size_t)FDIM * TPAD * sizeof(float)
                            + (size_t)FDIM * BLU * sizeof(float2); // 99,328 B
    cudaFuncSetAttribute(lrsig_gemm, cudaFuncAttributeMaxDynamicSharedMemorySize,
                         (int)smem_bytes);

    lrsig_gemm<<<dim3(TT / BT, LUDIM / BLU, BB), 256, smem_bytes>>>(x, kern);
    lrsig_scan<<<dim3(NCH, NCHAIN / 256), 256>>>();
    lrsig_combine<<<NCHAIN / 256, 256>>>((float*)d_out);
}

// round 7
// speedup vs baseline: 1.8997x; 1.8997x over previous
#include <cuda_runtime.h>
#include <cuda_bf16.h>
#include <cstdint>
#include <cstddef>

// Problem constants
#define BB    32
#define TT    2048
#define FIN   63
#define FDIM  64
#define LUDIM 640
#define NCH   64      // t-chunks for the parallel scan
#define TC    32      // timesteps per chunk
#define NCHAIN 2048   // B*U chains

// GEMM tiling: block tile 128t x 64lu, 8 warps (4 t-groups x 2 lu-groups),
// warp tile 32t x 32lu = (mt 0..1)x(nt 0..3) m16n8 fragments.
#define GBT  128
#define GBLU 64
#define XSTRIDE 72    // bf16 row stride (64 + 8 pad): ldmatrix rows hit distinct banks

// Scratch (allocation-free per harness rules). P[b][t][lu] (lu = l*64+u):
// scan warps (lanes = consecutive u) read contiguous 128B lines.
__device__ float g_P[(size_t)BB * TT * LUDIM];      // 167.8 MB
__device__ float g_W[(size_t)NCH * 17 * NCHAIN];    // 8.9 MB

// ---------------- PTX helpers ----------------
__device__ __forceinline__ uint32_t smem_u32(const void* p) {
    uint32_t a;
    asm("{ .reg .u64 t; cvta.to.shared.u64 t, %1; cvt.u32.u64 %0, t; }" : "=r"(a) : "l"(p));
    return a;
}
__device__ __forceinline__ void ldsm_x4(uint32_t& r0, uint32_t& r1, uint32_t& r2, uint32_t& r3,
                                        uint32_t addr) {
    asm volatile("ldmatrix.sync.aligned.m8n8.x4.shared.b16 {%0,%1,%2,%3}, [%4];"
                 : "=r"(r0), "=r"(r1), "=r"(r2), "=r"(r3) : "r"(addr));
}
__device__ __forceinline__ void mma_bf16(float* c, const uint32_t* a, uint32_t b0, uint32_t b1) {
    asm volatile(
        "mma.sync.aligned.m16n8k16.row.col.f32.bf16.bf16.f32 "
        "{%0,%1,%2,%3}, {%4,%5,%6,%7}, {%8,%9}, {%0,%1,%2,%3};"
        : "+f"(c[0]), "+f"(c[1]), "+f"(c[2]), "+f"(c[3])
        : "r"(a[0]), "r"(a[1]), "r"(a[2]), "r"(a[3]), "r"(b0), "r"(b1));
}

// ---------------- Kernel 1: P = X @ K via bf16 tensor cores ----------------
// fp32 accuracy via 3-term bf16 split: X=Xh+Xl, K=Kh+Kl;
// D = Xh*Kh + Xl*Kh + Xh*Kl  (dropped Xl*Kl ~ 2^-18 relative).
// Grid (16, 10, 32) = 5120 blocks, 256 threads.
extern "C" __global__ void __launch_bounds__(256, 2)
lrsig_gemm(const float* __restrict__ x, const float* __restrict__ kern)
{
    extern __shared__ char smem[];
    // byte offsets: Xh[128][72]bf16, Xl, KhT[64][72]bf16 ([lu][f]), KlT
    const int XH = 0, XL = 18432, KH = 36864, KL = 46080;   // total 55296 B
    const uint32_t sb = smem_u32(smem);

    const int tid  = threadIdx.x;
    const int lane = tid & 31;
    const int w    = tid >> 5;
    const int wt   = w >> 1;        // 0..3  (32-t group)
    const int wl   = w & 1;         // 0..1  (32-lu group)
    const int t0   = blockIdx.x * GBT;
    const int lu0  = blockIdx.y * GBLU;
    const int b    = blockIdx.z;

    // Fill X tiles (hi/lo split), row = t-local, col = f. Coalesced gmem reads.
    for (int e = tid; e < GBT * FDIM; e += 256) {
        int tl = e >> 6, f = e & 63;
        int t = t0 + tl;
        float v;
        if (f < FIN) v = x[((size_t)b * TT + t) * FIN + f];
        else         v = (float)t * (2.0f / 2047.0f) - 1.0f;
        __nv_bfloat16 hi = __float2bfloat16(v);
        __nv_bfloat16 lo = __float2bfloat16(v - __bfloat162float(hi));
        int off = tl * XSTRIDE * 2 + f * 2;
        *reinterpret_cast<__nv_bfloat16*>(smem + XH + off) = hi;
        *reinterpret_cast<__nv_bfloat16*>(smem + XL + off) = lo;
    }
    // Fill K^T tiles: [lu][f] bf16. Coalesced gmem reads (consecutive lu).
    for (int e = tid; e < FDIM * GBLU; e += 256) {
        int f = e >> 6, j = e & 63;
        float v = kern[f * LUDIM + lu0 + j];
        __nv_bfloat16 hi = __float2bfloat16(v);
        __nv_bfloat16 lo = __float2bfloat16(v - __bfloat162float(hi));
        int off = j * XSTRIDE * 2 + f * 2;
        *reinterpret_cast<__nv_bfloat16*>(smem + KH + off) = hi;
        *reinterpret_cast<__nv_bfloat16*>(smem + KL + off) = lo;
    }
    __syncthreads();

    // Per-lane ldmatrix row-address offsets (bytes).
    // A (16x16): lanes 0-15 -> rows (lane&15), k+0; lanes 16-31 -> rows, k+8.
    const uint32_t a_off = (uint32_t)((lane & 15) * XSTRIDE + ((lane >> 4) << 3)) * 2;
    // B (two n8 tiles x k16): n = ((lane>>4)<<3)+(lane&7), k = ((lane>>3)&1)*8.
    const uint32_t b_off = (uint32_t)(((((lane >> 4) << 3) + (lane & 7)) * XSTRIDE)
                                      + (((lane >> 3) & 1) << 3)) * 2;

    float C[2][4][4];
#pragma unroll
    for (int mt = 0; mt < 2; mt++)
#pragma unroll
        for (int nt = 0; nt < 4; nt++)
#pragma unroll
            for (int i = 0; i < 4; i++) C[mt][nt][i] = 0.0f;

#pragma unroll
    for (int ks = 0; ks < 4; ks++) {                 // K = 64 = 4 x k16
        uint32_t Ah[2][4], Al[2][4];
#pragma unroll
        for (int mt = 0; mt < 2; mt++) {
            uint32_t ra = sb + (uint32_t)((wt * 32 + mt * 16) * XSTRIDE + ks * 16) * 2 + a_off;
            ldsm_x4(Ah[mt][0], Ah[mt][1], Ah[mt][2], Ah[mt][3], ra + XH);
            ldsm_x4(Al[mt][0], Al[mt][1], Al[mt][2], Al[mt][3], ra + XL);
        }
#pragma unroll
        for (int q = 0; q < 2; q++) {                // nt pairs (2q, 2q+1)
            uint32_t rb = sb + (uint32_t)((wl * 32 + q * 16) * XSTRIDE + ks * 16) * 2 + b_off;
            uint32_t Bh[4], Bl[4];
            ldsm_x4(Bh[0], Bh[1], Bh[2], Bh[3], rb + KH);
            ldsm_x4(Bl[0], Bl[1], Bl[2], Bl[3], rb + KL);
#pragma unroll
            for (int mt = 0; mt < 2; mt++)
#pragma unroll
                for (int p = 0; p < 2; p++) {
                    float* c = C[mt][q * 2 + p];
                    mma_bf16(c, Ah[mt], Bh[p * 2], Bh[p * 2 + 1]);
                    mma_bf16(c, Al[mt], Bh[p * 2], Bh[p * 2 + 1]);
                    mma_bf16(c, Ah[mt], Bl[p * 2], Bl[p * 2 + 1]);
                }
        }
    }

    // Epilogue: c0,c1 -> (t = base + lane>>2, lu pair), c2,c3 -> t+8.
#pragma unroll
    for (int mt = 0; mt < 2; mt++) {
        int tr = t0 + wt * 32 + mt * 16 + (lane >> 2);
#pragma unroll
        for (int nt = 0; nt < 4; nt++) {
            int lu = lu0 + wl * 32 + nt * 8 + (lane & 3) * 2;
            float* p0 = g_P + ((size_t)b * TT + tr) * LUDIM + lu;
            float* p1 = p0 + (size_t)8 * LUDIM;
            *reinterpret_cast<float2*>(p0) = make_float2(C[mt][nt][0], C[mt][nt][1]);
            *reinterpret_cast<float2*>(p1) = make_float2(C[mt][nt][2], C[mt][nt][3]);
        }
    }
}

// ---------------- Kernel 2: per-chunk scan coefficients (round-3 form) ----------------
extern "C" __global__ void __launch_bounds__(256)
lrsig_scan(void)
{
    const int c     = blockIdx.x;
    const int chain = blockIdx.y * 256 + threadIdx.x;
    const int b = chain >> 6;
    const int u = chain & 63;

    const float* base = g_P + (size_t)b * TT * LUDIM + u;
    const int t0 = c * TC;
    const int tp = (c == 0) ? 0 : (t0 - 1);

    float prev[10];
#pragma unroll
    for (int l = 0; l < 10; l++) prev[l] = base[(size_t)tp * LUDIM + l * 64];

    float e1=0.f,e3=0.f,e4=0.f,e43=0.f,e6=0.f,e7=0.f,e76=0.f,e8=0.f,e87=0.f,e876=0.f;
    float S2=0.f,S5=0.f,S9=0.f,W21=0.f,W54=0.f,W543=0.f,W98=0.f,W987=0.f,W9876=0.f,y0=0.f;

#pragma unroll 4
    for (int i = 0; i < TC; i++) {
        const float* p = base + (size_t)(t0 + i) * LUDIM;
        float m[10];
#pragma unroll
        for (int l = 0; l < 10; l++) {
            float v = p[l * 64];
            m[l] = v - prev[l];
            prev[l] = v;
        }
        // All RHS use pre-update (exclusive) values.
        y0   += m[0];
        W21   = fmaf(m[2], e1,   W21);   S2 += m[2];
        W54   = fmaf(m[5], e4,   W54);
        W543  = fmaf(m[5], e43,  W543);  S5 += m[5];
        W98   = fmaf(m[9], e8,   W98);
        W987  = fmaf(m[9], e87,  W987);
        W9876 = fmaf(m[9], e876, W9876); S9 += m[9];
        e43   = fmaf(m[4], e3,   e43);
        e876  = fmaf(m[8], e76,  e876);
        e87   = fmaf(m[8], e7,   e87);
        e76   = fmaf(m[7], e6,   e76);
        e1 += m[1]; e3 += m[3]; e4 += m[4];
        e6 += m[6]; e7 += m[7]; e8 += m[8];
    }

    float* w = g_W + (size_t)c * 17 * NCHAIN + chain;
    w[ 0 * NCHAIN] = y0 + W21 + W543 + W9876;
    w[ 1 * NCHAIN] = S2;   w[ 2 * NCHAIN] = S5;   w[ 3 * NCHAIN] = S9;
    w[ 4 * NCHAIN] = W54;  w[ 5 * NCHAIN] = W98;  w[ 6 * NCHAIN] = W987;
    w[ 7 * NCHAIN] = e1;   w[ 8 * NCHAIN] = e3;   w[ 9 * NCHAIN] = e4;
    w[10 * NCHAIN] = e43;  w[11 * NCHAIN] = e6;   w[12 * NCHAIN] = e7;
    w[13 * NCHAIN] = e76;  w[14 * NCHAIN] = e8;   w[15 * NCHAIN] = e87;
    w[16 * NCHAIN] = e876;
}

// ---------------- Kernel 3: warp-tree combine ----------------
// Chunk maps compose associatively (Chen). One warp per chain: lane folds
// 2 chunks, then 5 shfl-compose levels; lane 0 holds the full map; Y = Y0
// (initial state is zero).
struct SigMap {
    float Y0,S2,S5,S9,W54,W98,W987,E1,E3,E4,E43,E6,E7,E76,E8,E87,E876;
};

__device__ __forceinline__ SigMap sig_load(int c, int chain) {
    const float* w = g_W + (size_t)c * 17 * NCHAIN + chain;
    SigMap m;
    m.Y0  = w[0*NCHAIN];  m.S2  = w[1*NCHAIN];  m.S5  = w[2*NCHAIN];
    m.S9  = w[3*NCHAIN];  m.W54 = w[4*NCHAIN];  m.W98 = w[5*NCHAIN];
    m.W987= w[6*NCHAIN];  m.E1  = w[7*NCHAIN];  m.E3  = w[8*NCHAIN];
    m.E4  = w[9*NCHAIN];  m.E43 = w[10*NCHAIN]; m.E6  = w[11*NCHAIN];
    m.E7  = w[12*NCHAIN]; m.E76 = w[13*NCHAIN]; m.E8  = w[14*NCHAIN];
    m.E87 = w[15*NCHAIN]; m.E876= w[16*NCHAIN];
    return m;
}

// C = B after A (A covers earlier chunks)
__device__ __forceinline__ SigMap sig_compose(const SigMap& A, const SigMap& B) {
    SigMap C;
    C.E1   = A.E1 + B.E1;
    C.E3   = A.E3 + B.E3;
    C.E6   = A.E6 + B.E6;
    C.E4   = A.E4 + B.E4;
    C.E43  = A.E43 + A.E3 * B.E4 + B.E43;
    C.E7   = A.E7 + B.E7;
    C.E76  = A.E76 + A.E6 * B.E7 + B.E76;
    C.E8   = A.E8 + B.E8;
    C.E87  = A.E87 + A.E7 * B.E8 + B.E87;
    C.E876 = A.E876 + A.E76 * B.E8 + A.E6 * B.E87 + B.E876;
    C.S2   = A.S2 + B.S2;
    C.S5   = A.S5 + B.S5;
    C.S9   = A.S9 + B.S9;
    C.W54  = A.W54 + A.E4 * B.S5 + B.W54;
    C.W98  = A.W98 + A.E8 * B.S9 + B.W98;
    C.W987 = A.W987 + A.E87 * B.S9 + A.E7 * B.W98 + B.W987;
    C.Y0   = A.Y0 + B.Y0 + A.E1 * B.S2 + A.E43 * B.S5 + A.E3 * B.W54
           + A.E876 * B.S9 + A.E76 * B.W98 + A.E6 * B.W987;
    return C;
}

__device__ __forceinline__ SigMap sig_shfl_down(const SigMap& m, int o) {
    SigMap r;
    r.Y0  = __shfl_down_sync(0xffffffffu, m.Y0,  o);
    r.S2  = __shfl_down_sync(0xffffffffu, m.S2,  o);
    r.S5  = __shfl_down_sync(0xffffffffu, m.S5,  o);
    r.S9  = __shfl_down_sync(0xffffffffu, m.S9,  o);
    r.W54 = __shfl_down_sync(0xffffffffu, m.W54, o);
    r.W98 = __shfl_down_sync(0xffffffffu, m.W98, o);
    r.W987= __shfl_down_sync(0xffffffffu, m.W987,o);
    r.E1  = __shfl_down_sync(0xffffffffu, m.E1,  o);
    r.E3  = __shfl_down_sync(0xffffffffu, m.E3,  o);
    r.E4  = __shfl_down_sync(0xffffffffu, m.E4,  o);
    r.E43 = __shfl_down_sync(0xffffffffu, m.E43, o);
    r.E6  = __shfl_down_sync(0xffffffffu, m.E6,  o);
    r.E7  = __shfl_down_sync(0xffffffffu, m.E7,  o);
    r.E76 = __shfl_down_sync(0xffffffffu, m.E76, o);
    r.E8  = __shfl_down_sync(0xffffffffu, m.E8,  o);
    r.E87 = __shfl_down_sync(0xffffffffu, m.E87, o);
    r.E876= __shfl_down_sync(0xffffffffu, m.E876,o);
    return r;
}

extern "C" __global__ void __launch_bounds__(256)
lrsig_combine(float* __restrict__ out)
{
    const int chain = blockIdx.x * 8 + (threadIdx.x >> 5);
    const int lane  = threadIdx.x & 31;

    SigMap M = sig_compose(sig_load(2 * lane, chain), sig_load(2 * lane + 1, chain));
#pragma unroll
    for (int o = 1; o < 32; o <<= 1)
        M = sig_compose(M, sig_shfl_down(M, o));   // high lanes hold junk; lane 0 exact

    if (lane == 0) out[chain] = M.Y0;   // initial state is zero -> Y = Y0
}

// ---------------- Launch ----------------
extern "C" void kernel_launch(void* const* d_in, const int* in_sizes, int n_in,
                              void* d_out, int out_size)
{
    const float* x    = (const float*)d_in[0];  // (32, 2048, 63) f32
    const float* kern = (const float*)d_in[1];  // (64, 10, 64)  f32

    const int smem_bytes = 55296;
    cudaFuncSetAttribute(lrsig_gemm, cudaFuncAttributeMaxDynamicSharedMemorySize, smem_bytes);

    lrsig_gemm<<<dim3(TT / GBT, LUDIM / GBLU, BB), 256, smem_bytes>>>(x, kern);
    lrsig_scan<<<dim3(NCH, NCHAIN / 256), 256>>>();
    lrsig_combine<<<NCHAIN / 8, 256>>>((float*)d_out);
}

// round 8
// speedup vs baseline: 2.5359x; 1.3349x over previous
#include <cuda_runtime.h>
#include <cuda_bf16.h>
#include <cstdint>
#include <cstddef>

// Problem constants
#define BB     32
#define TT     2048
#define FIN    63
#define FDIM   64
#define LUDIM  640
#define NCH    32      // chunks of 64 timesteps
#define TCH    64
#define NCHAIN 2048

// smem byte offsets (fused kernel)
#define XSTR   72      // X row stride (bf16 elems)
#define KSTR   136     // K row stride (bf16 elems), [f][lu] layout
#define PSTR   648     // sP row stride (floats)
#define OFF_XH 0
#define OFF_XL 9216            // 64*72*2
#define OFF_KH 18432
#define OFF_KL 35840           // +64*136*2
#define OFF_SP 53248           // +64*136*2
#define SMEM_TOTAL (OFF_SP + 65 * PSTR * 4)   // 53248 + 168480 = 221728

__device__ float g_W[(size_t)NCH * 17 * NCHAIN];    // 4.5 MB

// ---------------- PTX helpers ----------------
__device__ __forceinline__ uint32_t smem_u32(const void* p) {
    uint32_t a;
    asm("{ .reg .u64 t; cvta.to.shared.u64 t, %1; cvt.u32.u64 %0, t; }" : "=r"(a) : "l"(p));
    return a;
}
__device__ __forceinline__ void ldsm_x4(uint32_t& r0, uint32_t& r1, uint32_t& r2, uint32_t& r3,
                                        uint32_t addr) {
    asm volatile("ldmatrix.sync.aligned.m8n8.x4.shared.b16 {%0,%1,%2,%3}, [%4];"
                 : "=r"(r0), "=r"(r1), "=r"(r2), "=r"(r3) : "r"(addr));
}
__device__ __forceinline__ void ldsm_x4t(uint32_t& r0, uint32_t& r1, uint32_t& r2, uint32_t& r3,
                                         uint32_t addr) {
    asm volatile("ldmatrix.sync.aligned.m8n8.x4.trans.shared.b16 {%0,%1,%2,%3}, [%4];"
                 : "=r"(r0), "=r"(r1), "=r"(r2), "=r"(r3) : "r"(addr));
}
__device__ __forceinline__ void mma_bf16(float* c, const uint32_t* a, uint32_t b0, uint32_t b1) {
    asm volatile(
        "mma.sync.aligned.m16n8k16.row.col.f32.bf16.bf16.f32 "
        "{%0,%1,%2,%3}, {%4,%5,%6,%7}, {%8,%9}, {%0,%1,%2,%3};"
        : "+f"(c[0]), "+f"(c[1]), "+f"(c[2]), "+f"(c[3])
        : "r"(a[0]), "r"(a[1]), "r"(a[2]), "r"(a[3]), "r"(b0), "r"(b1));
}

// ---------------- Fused kernel: GEMM tile (in smem) + chunk scan ----------------
// Grid (NCH, BB) = (32, 32), 256 threads, 1 CTA/SM.
// Block (c, b): computes P[t][lu] for t in [64c, 64c+63], ALL 640 lu, into smem
// rows 1..64; row 0 = P[max(64c-1,0)] via fp32 FFMA. Then 64 threads run the
// per-chain scan over the tile and emit 17 Chen coefficients to g_W.
extern "C" __global__ void __launch_bounds__(256, 1)
lrsig_fused(const float* __restrict__ x, const float* __restrict__ kern)
{
    extern __shared__ char smem[];
    float* sP = reinterpret_cast<float*>(smem + OFF_SP);
    const uint32_t sb = smem_u32(smem);

    const int tid  = threadIdx.x;
    const int lane = tid & 31;
    const int w    = tid >> 5;          // warp 0..7 -> n16 group within stage
    const int c    = blockIdx.x;
    const int b    = blockIdx.y;
    const int t0   = c * TCH;

    // ---- Fill X tile (hi/lo bf16 split), rows t0..t0+63, [t][f], stride 72 ----
    for (int e = tid; e < TCH * FDIM; e += 256) {
        int tl = e >> 6, f = e & 63;
        int t = t0 + tl;
        float v;
        if (f < FIN) v = x[((size_t)b * TT + t) * FIN + f];
        else         v = (float)t * (2.0f / 2047.0f) - 1.0f;
        __nv_bfloat16 hi = __float2bfloat16(v);
        __nv_bfloat16 lo = __float2bfloat16(v - __bfloat162float(hi));
        int off = (tl * XSTR + f) * 2;
        *reinterpret_cast<__nv_bfloat16*>(smem + OFF_XH + off) = hi;
        *reinterpret_cast<__nv_bfloat16*>(smem + OFF_XL + off) = lo;
    }

    // ---- Prev row: sP[0][j] = P[max(t0-1,0)][j], exact fp32 FFMA ----
    {
        const int tp = (c == 0) ? 0 : (t0 - 1);
        const float* xr = x + ((size_t)b * TT + tp) * FIN;
        const float tfeat = (float)tp * (2.0f / 2047.0f) - 1.0f;
        for (int j = tid; j < LUDIM; j += 256) {
            float acc = tfeat * kern[63 * LUDIM + j];
            for (int f = 0; f < FIN; f++)
                acc = fmaf(xr[f], kern[f * LUDIM + j], acc);
            sP[j] = acc;
        }
    }
    __syncthreads();

    // ---- Preload A fragments (reused across all 5 stages) ----
    // a_off: lanes 0-15 rows, lanes 16-31 rows with k+8 (round-7 verified).
    const uint32_t a_off = (uint32_t)((lane & 15) * XSTR + ((lane >> 4) << 3)) * 2;
    uint32_t Ah[4][4][4], Al[4][4][4];
#pragma unroll
    for (int mt = 0; mt < 4; mt++)
#pragma unroll
        for (int ks = 0; ks < 4; ks++) {
            uint32_t ra = (uint32_t)(mt * 16 * XSTR + ks * 16) * 2 + a_off;
            ldsm_x4(Ah[mt][ks][0], Ah[mt][ks][1], Ah[mt][ks][2], Ah[mt][ks][3],
                    sb + OFF_XH + ra);
            ldsm_x4(Al[mt][ks][0], Al[mt][ks][1], Al[mt][ks][2], Al[mt][ks][3],
                    sb + OFF_XL + ra);
        }

    // B ldsm.trans lane offset: K stored [f][lu], stride 136.
    // group g = lane>>3: k_off = (g&1)*8, n_off = (g>>1)*8, row = k + (lane&7).
    const uint32_t b_off = (uint32_t)((((lane >> 3) & 1) * 8 + (lane & 7)) * KSTR
                                      + ((lane >> 4) << 3)) * 2;

    // ---- Stage loop: 5 stages of 128 lu ----
    for (int s = 0; s < 5; s++) {
        __syncthreads();   // prior stage's ldsm reads complete before refill
        // Fill K^T stage tile: [f][j] bf16 hi/lo, j = lu - 128s. Coalesced
        // gmem reads (consecutive j) and conflict-free STS (consecutive j).
        for (int e = tid; e < FDIM * 128; e += 256) {
            int j = e & 127, f = e >> 7;
            float v = kern[f * LUDIM + s * 128 + j];
            __nv_bfloat16 hi = __float2bfloat16(v);
            __nv_bfloat16 lo = __float2bfloat16(v - __bfloat162float(hi));
            int off = (f * KSTR + j) * 2;
            *reinterpret_cast<__nv_bfloat16*>(smem + OFF_KH + off) = hi;
            *reinterpret_cast<__nv_bfloat16*>(smem + OFF_KL + off) = lo;
        }
        __syncthreads();

        float C[4][2][4];
#pragma unroll
        for (int mt = 0; mt < 4; mt++)
#pragma unroll
            for (int p = 0; p < 2; p++)
#pragma unroll
                for (int i = 0; i < 4; i++) C[mt][p][i] = 0.0f;

#pragma unroll
        for (int ks = 0; ks < 4; ks++) {
            uint32_t rb = (uint32_t)(ks * 16 * KSTR + w * 16) * 2 + b_off;
            uint32_t Bh[4], Bl[4];
            ldsm_x4t(Bh[0], Bh[1], Bh[2], Bh[3], sb + OFF_KH + rb);
            ldsm_x4t(Bl[0], Bl[1], Bl[2], Bl[3], sb + OFF_KL + rb);
#pragma unroll
            for (int mt = 0; mt < 4; mt++)
#pragma unroll
                for (int p = 0; p < 2; p++) {
                    float* cc = C[mt][p];
                    mma_bf16(cc, Ah[mt][ks], Bh[p * 2], Bh[p * 2 + 1]);
                    mma_bf16(cc, Al[mt][ks], Bh[p * 2], Bh[p * 2 + 1]);
                    mma_bf16(cc, Ah[mt][ks], Bl[p * 2], Bl[p * 2 + 1]);
                }
        }

        // Epilogue into sP rows 1..64 (row = t-local + 1)
#pragma unroll
        for (int mt = 0; mt < 4; mt++) {
            int r = mt * 16 + (lane >> 2);
#pragma unroll
            for (int p = 0; p < 2; p++) {
                int col = s * 128 + w * 16 + p * 8 + (lane & 3) * 2;
                float* q0 = sP + (size_t)(r + 1) * PSTR + col;
                float* q1 = sP + (size_t)(r + 9) * PSTR + col;
                *reinterpret_cast<float2*>(q0) = make_float2(C[mt][p][0], C[mt][p][1]);
                *reinterpret_cast<float2*>(q1) = make_float2(C[mt][p][2], C[mt][p][3]);
            }
        }
    }
    __syncthreads();

    // ---- Scan: 64 threads, one chain (b, u) each, 64 steps from smem ----
    if (tid < 64) {
        const int u = tid;
        float prev[10];
#pragma unroll
        for (int l = 0; l < 10; l++) prev[l] = sP[l * 64 + u];   // row 0

        float e1=0.f,e3=0.f,e4=0.f,e43=0.f,e6=0.f,e7=0.f,e76=0.f,e8=0.f,e87=0.f,e876=0.f;
        float S2=0.f,S5=0.f,S9=0.f,W21=0.f,W54=0.f,W543=0.f,W98=0.f,W987=0.f,W9876=0.f,y0=0.f;

#pragma unroll 4
        for (int i = 1; i <= TCH; i++) {
            const float* p = sP + (size_t)i * PSTR + u;
            float m[10];
#pragma unroll
            for (int l = 0; l < 10; l++) {
                float v = p[l * 64];
                m[l] = v - prev[l];
                prev[l] = v;
            }
            // All RHS use pre-update (exclusive) values.
            y0   += m[0];
            W21   = fmaf(m[2], e1,   W21);   S2 += m[2];
            W54   = fmaf(m[5], e4,   W54);
            W543  = fmaf(m[5], e43,  W543);  S5 += m[5];
            W98   = fmaf(m[9], e8,   W98);
            W987  = fmaf(m[9], e87,  W987);
            W9876 = fmaf(m[9], e876, W9876); S9 += m[9];
            e43   = fmaf(m[4], e3,   e43);
            e876  = fmaf(m[8], e76,  e876);
            e87   = fmaf(m[8], e7,   e87);
            e76   = fmaf(m[7], e6,   e76);
            e1 += m[1]; e3 += m[3]; e4 += m[4];
            e6 += m[6]; e7 += m[7]; e8 += m[8];
        }

        const int chain = b * 64 + u;
        float* wp = g_W + (size_t)c * 17 * NCHAIN + chain;
        wp[ 0 * NCHAIN] = y0 + W21 + W543 + W9876;
        wp[ 1 * NCHAIN] = S2;   wp[ 2 * NCHAIN] = S5;   wp[ 3 * NCHAIN] = S9;
        wp[ 4 * NCHAIN] = W54;  wp[ 5 * NCHAIN] = W98;  wp[ 6 * NCHAIN] = W987;
        wp[ 7 * NCHAIN] = e1;   wp[ 8 * NCHAIN] = e3;   wp[ 9 * NCHAIN] = e4;
        wp[10 * NCHAIN] = e43;  wp[11 * NCHAIN] = e6;   wp[12 * NCHAIN] = e7;
        wp[13 * NCHAIN] = e76;  wp[14 * NCHAIN] = e8;   wp[15 * NCHAIN] = e87;
        wp[16 * NCHAIN] = e876;
    }
}

// ---------------- Combine: warp-tree composition (Chen), 32 chunks ----------------
struct SigMap {
    float Y0,S2,S5,S9,W54,W98,W987,E1,E3,E4,E43,E6,E7,E76,E8,E87,E876;
};

__device__ __forceinline__ SigMap sig_load(int c, int chain) {
    const float* w = g_W + (size_t)c * 17 * NCHAIN + chain;
    SigMap m;
    m.Y0  = w[0*NCHAIN];  m.S2  = w[1*NCHAIN];  m.S5  = w[2*NCHAIN];
    m.S9  = w[3*NCHAIN];  m.W54 = w[4*NCHAIN];  m.W98 = w[5*NCHAIN];
    m.W987= w[6*NCHAIN];  m.E1  = w[7*NCHAIN];  m.E3  = w[8*NCHAIN];
    m.E4  = w[9*NCHAIN];  m.E43 = w[10*NCHAIN]; m.E6  = w[11*NCHAIN];
    m.E7  = w[12*NCHAIN]; m.E76 = w[13*NCHAIN]; m.E8  = w[14*NCHAIN];
    m.E87 = w[15*NCHAIN]; m.E876= w[16*NCHAIN];
    return m;
}

// C = B after A (A covers earlier chunks)
__device__ __forceinline__ SigMap sig_compose(const SigMap& A, const SigMap& B) {
    SigMap C;
    C.E1   = A.E1 + B.E1;
    C.E3   = A.E3 + B.E3;
    C.E6   = A.E6 + B.E6;
    C.E4   = A.E4 + B.E4;
    C.E43  = A.E43 + A.E3 * B.E4 + B.E43;
    C.E7   = A.E7 + B.E7;
    C.E76  = A.E76 + A.E6 * B.E7 + B.E76;
    C.E8   = A.E8 + B.E8;
    C.E87  = A.E87 + A.E7 * B.E8 + B.E87;
    C.E876 = A.E876 + A.E76 * B.E8 + A.E6 * B.E87 + B.E876;
    C.S2   = A.S2 + B.S2;
    C.S5   = A.S5 + B.S5;
    C.S9   = A.S9 + B.S9;
    C.W54  = A.W54 + A.E4 * B.S5 + B.W54;
    C.W98  = A.W98 + A.E8 * B.S9 + B.W98;
    C.W987 = A.W987 + A.E87 * B.S9 + A.E7 * B.W98 + B.W987;
    C.Y0   = A.Y0 + B.Y0 + A.E1 * B.S2 + A.E43 * B.S5 + A.E3 * B.W54
           + A.E876 * B.S9 + A.E76 * B.W98 + A.E6 * B.W987;
    return C;
}

__device__ __forceinline__ SigMap sig_shfl_down(const SigMap& m, int o) {
    SigMap r;
    r.Y0  = __shfl_down_sync(0xffffffffu, m.Y0,  o);
    r.S2  = __shfl_down_sync(0xffffffffu, m.S2,  o);
    r.S5  = __shfl_down_sync(0xffffffffu, m.S5,  o);
    r.S9  = __shfl_down_sync(0xffffffffu, m.S9,  o);
    r.W54 = __shfl_down_sync(0xffffffffu, m.W54, o);
    r.W98 = __shfl_down_sync(0xffffffffu, m.W98, o);
    r.W987= __shfl_down_sync(0xffffffffu, m.W987,o);
    r.E1  = __shfl_down_sync(0xffffffffu, m.E1,  o);
    r.E3  = __shfl_down_sync(0xffffffffu, m.E3,  o);
    r.E4  = __shfl_down_sync(0xffffffffu, m.E4,  o);
    r.E43 = __shfl_down_sync(0xffffffffu, m.E43, o);
    r.E6  = __shfl_down_sync(0xffffffffu, m.E6,  o);
    r.E7  = __shfl_down_sync(0xffffffffu, m.E7,  o);
    r.E76 = __shfl_down_sync(0xffffffffu, m.E76, o);
    r.E8  = __shfl_down_sync(0xffffffffu, m.E8,  o);
    r.E87 = __shfl_down_sync(0xffffffffu, m.E87, o);
    r.E876= __shfl_down_sync(0xffffffffu, m.E876,o);
    return r;
}

extern "C" __global__ void __launch_bounds__(256)
lrsig_combine(float* __restrict__ out)
{
    const int chain = blockIdx.x * 8 + (threadIdx.x >> 5);
    const int lane  = threadIdx.x & 31;

    SigMap M = sig_load(lane, chain);   // chunk = lane (NCH = 32)
#pragma unroll
    for (int o = 1; o < 32; o <<= 1)
        M = sig_compose(M, sig_shfl_down(M, o));   // lane 0 exact after tree

    if (lane == 0) out[chain] = M.Y0;   // initial state zero -> Y = Y0
}

// ---------------- Launch ----------------
extern "C" void kernel_launch(void* const* d_in, const int* in_sizes, int n_in,
                              void* d_out, int out_size)
{
    const float* x    = (const float*)d_in[0];  // (32, 2048, 63) f32
    const float* kern = (const float*)d_in[1];  // (64, 10, 64)  f32

    cudaFuncSetAttribute(lrsig_fused, cudaFuncAttributeMaxDynamicSharedMemorySize,
                         SMEM_TOTAL);

    lrsig_fused<<<dim3(NCH, BB), 256, SMEM_TOTAL>>>(x, kern);
    lrsig_combine<<<NCHAIN / 8, 256>>>((float*)d_out);
}

// round 9
// speedup vs baseline: 2.6033x; 1.0266x over previous
#include <cuda_runtime.h>
#include <cuda_bf16.h>
#include <cstdint>
#include <cstddef>

// Problem constants
#define BB     32
#define TT     2048
#define FIN    63
#define FDIM   64
#define LUDIM  640
#define NCH    32      // chunks of 64 timesteps
#define TCH    64
#define NCHAIN 2048

// smem byte offsets (fused kernel)
#define XSTR   72      // X row stride (bf16 elems)
#define KSTR   136     // K row stride (bf16 elems), [f][lu] layout
#define PSTR   648     // sP row stride (floats)
#define OFF_XH 0
#define OFF_XL 9216            // 64*72*2
#define OFF_KH 18432
#define OFF_KL 35840           // +64*136*2
#define OFF_SP 53248
#define SMEM_TOTAL (OFF_SP + 65 * PSTR * 4)   // 221728 B
// sub-chunk SigMaps staged over the K region after the stage loop
#define OFF_MAPS OFF_KH        // 4*64*17*4 = 17408 B <= K region

// g_W layout: [chain][c][17]  (combine reads coalesced)
__device__ float g_W[(size_t)NCHAIN * NCH * 17];    // 4.5 MB

// ---------------- PTX helpers ----------------
__device__ __forceinline__ uint32_t smem_u32(const void* p) {
    uint32_t a;
    asm("{ .reg .u64 t; cvta.to.shared.u64 t, %1; cvt.u32.u64 %0, t; }" : "=r"(a) : "l"(p));
    return a;
}
__device__ __forceinline__ void ldsm_x4(uint32_t& r0, uint32_t& r1, uint32_t& r2, uint32_t& r3,
                                        uint32_t addr) {
    asm volatile("ldmatrix.sync.aligned.m8n8.x4.shared.b16 {%0,%1,%2,%3}, [%4];"
                 : "=r"(r0), "=r"(r1), "=r"(r2), "=r"(r3) : "r"(addr));
}
__device__ __forceinline__ void ldsm_x4t(uint32_t& r0, uint32_t& r1, uint32_t& r2, uint32_t& r3,
                                         uint32_t addr) {
    asm volatile("ldmatrix.sync.aligned.m8n8.x4.trans.shared.b16 {%0,%1,%2,%3}, [%4];"
                 : "=r"(r0), "=r"(r1), "=r"(r2), "=r"(r3) : "r"(addr));
}
__device__ __forceinline__ void mma_bf16(float* c, const uint32_t* a, uint32_t b0, uint32_t b1) {
    asm volatile(
        "mma.sync.aligned.m16n8k16.row.col.f32.bf16.bf16.f32 "
        "{%0,%1,%2,%3}, {%4,%5,%6,%7}, {%8,%9}, {%0,%1,%2,%3};"
        : "+f"(c[0]), "+f"(c[1]), "+f"(c[2]), "+f"(c[3])
        : "r"(a[0]), "r"(a[1]), "r"(a[2]), "r"(a[3]), "r"(b0), "r"(b1));
}

// ---------------- Chen map: 17 coefficients ----------------
struct SigMap {
    float Y0,S2,S5,S9,W54,W98,W987,E1,E3,E4,E43,E6,E7,E76,E8,E87,E876;
};

// C = B after A (A covers earlier time)
__device__ __forceinline__ SigMap sig_compose(const SigMap& A, const SigMap& B) {
    SigMap C;
    C.E1   = A.E1 + B.E1;
    C.E3   = A.E3 + B.E3;
    C.E6   = A.E6 + B.E6;
    C.E4   = A.E4 + B.E4;
    C.E43  = A.E43 + A.E3 * B.E4 + B.E43;
    C.E7   = A.E7 + B.E7;
    C.E76  = A.E76 + A.E6 * B.E7 + B.E76;
    C.E8   = A.E8 + B.E8;
    C.E87  = A.E87 + A.E7 * B.E8 + B.E87;
    C.E876 = A.E876 + A.E76 * B.E8 + A.E6 * B.E87 + B.E876;
    C.S2   = A.S2 + B.S2;
    C.S5   = A.S5 + B.S5;
    C.S9   = A.S9 + B.S9;
    C.W54  = A.W54 + A.E4 * B.S5 + B.W54;
    C.W98  = A.W98 + A.E8 * B.S9 + B.W98;
    C.W987 = A.W987 + A.E87 * B.S9 + A.E7 * B.W98 + B.W987;
    C.Y0   = A.Y0 + B.Y0 + A.E1 * B.S2 + A.E43 * B.S5 + A.E3 * B.W54
           + A.E876 * B.S9 + A.E76 * B.W98 + A.E6 * B.W987;
    return C;
}

// ---------------- Fused kernel: GEMM tile in smem + 4-way chunk scan ----------------
// Grid (NCH, BB) = (32, 32), 256 threads, 1 CTA/SM.
extern "C" __global__ void __launch_bounds__(256, 1)
lrsig_fused(const float* __restrict__ x, const float* __restrict__ kern)
{
    extern __shared__ char smem[];
    float* sP = reinterpret_cast<float*>(smem + OFF_SP);
    const uint32_t sb = smem_u32(smem);

    const int tid  = threadIdx.x;
    const int lane = tid & 31;
    const int w    = tid >> 5;
    const int wt   = w & 1;        // t half (32 rows)
    const int wn   = w >> 1;       // lu quarter within 128-wide stage
    const int c    = blockIdx.x;
    const int b    = blockIdx.y;
    const int t0   = c * TCH;

    // ---- X tile (hi/lo bf16 split), [t][f], stride 72 ----
    for (int e = tid; e < TCH * FDIM; e += 256) {
        int tl = e >> 6, f = e & 63;
        int t = t0 + tl;
        float v;
        if (f < FIN) v = x[((size_t)b * TT + t) * FIN + f];
        else         v = (float)t * (2.0f / 2047.0f) - 1.0f;
        __nv_bfloat16 hi = __float2bfloat16(v);
        __nv_bfloat16 lo = __float2bfloat16(v - __bfloat162float(hi));
        int off = (tl * XSTR + f) * 2;
        *reinterpret_cast<__nv_bfloat16*>(smem + OFF_XH + off) = hi;
        *reinterpret_cast<__nv_bfloat16*>(smem + OFF_XL + off) = lo;
    }

    // ---- Prev row: sP[0][j] = P[max(t0-1,0)][j], exact fp32 ----
    {
        const int tp = (c == 0) ? 0 : (t0 - 1);
        const float* xr = x + ((size_t)b * TT + tp) * FIN;
        const float tfeat = (float)tp * (2.0f / 2047.0f) - 1.0f;
        for (int j = tid; j < LUDIM; j += 256) {
            float acc = tfeat * kern[63 * LUDIM + j];
            for (int f = 0; f < FIN; f++)
                acc = fmaf(xr[f], kern[f * LUDIM + j], acc);
            sP[j] = acc;
        }
    }

    // ldmatrix lane offsets (verified rounds 7/8)
    const uint32_t a_off = (uint32_t)((lane & 15) * XSTR + ((lane >> 4) << 3)) * 2;
    const uint32_t b_off = (uint32_t)((((lane >> 3) & 1) * 8 + (lane & 7)) * KSTR
                                      + ((lane >> 4) << 3)) * 2;

    // ---- Stage loop: 5 stages of 128 lu; warp tile 32t x 32lu ----
    for (int s = 0; s < 5; s++) {
        __syncthreads();   // prior stage's ldsm reads (and init fills) complete
        for (int e = tid; e < FDIM * 128; e += 256) {
            int j = e & 127, f = e >> 7;
            float v = kern[f * LUDIM + s * 128 + j];
            __nv_bfloat16 hi = __float2bfloat16(v);
            __nv_bfloat16 lo = __float2bfloat16(v - __bfloat162float(hi));
            int off = (f * KSTR + j) * 2;
            *reinterpret_cast<__nv_bfloat16*>(smem + OFF_KH + off) = hi;
            *reinterpret_cast<__nv_bfloat16*>(smem + OFF_KL + off) = lo;
        }
        __syncthreads();

        float C[2][4][4];
#pragma unroll
        for (int mt = 0; mt < 2; mt++)
#pragma unroll
            for (int nt = 0; nt < 4; nt++)
#pragma unroll
                for (int i = 0; i < 4; i++) C[mt][nt][i] = 0.0f;

#pragma unroll
        for (int ks = 0; ks < 4; ks++) {
            uint32_t Ah[2][4], Al[2][4];
#pragma unroll
            for (int mt = 0; mt < 2; mt++) {
                uint32_t ra = (uint32_t)((wt * 32 + mt * 16) * XSTR + ks * 16) * 2 + a_off;
                ldsm_x4(Ah[mt][0], Ah[mt][1], Ah[mt][2], Ah[mt][3], sb + OFF_XH + ra);
                ldsm_x4(Al[mt][0], Al[mt][1], Al[mt][2], Al[mt][3], sb + OFF_XL + ra);
            }
#pragma unroll
            for (int q = 0; q < 2; q++) {
                uint32_t rb = (uint32_t)(ks * 16 * KSTR + (wn * 32 + q * 16)) * 2 + b_off;
                uint32_t Bh[4], Bl[4];
                ldsm_x4t(Bh[0], Bh[1], Bh[2], Bh[3], sb + OFF_KH + rb);
                ldsm_x4t(Bl[0], Bl[1], Bl[2], Bl[3], sb + OFF_KL + rb);
#pragma unroll
                for (int mt = 0; mt < 2; mt++)
#pragma unroll
                    for (int p = 0; p < 2; p++) {
                        float* cc = C[mt][q * 2 + p];
                        mma_bf16(cc, Ah[mt], Bh[p * 2], Bh[p * 2 + 1]);
                        mma_bf16(cc, Al[mt], Bh[p * 2], Bh[p * 2 + 1]);
                        mma_bf16(cc, Ah[mt], Bl[p * 2], Bl[p * 2 + 1]);
                    }
            }
        }

        // Epilogue into sP rows 1..64 (row = t-local + 1)
#pragma unroll
        for (int mt = 0; mt < 2; mt++) {
            int r = wt * 32 + mt * 16 + (lane >> 2);
#pragma unroll
            for (int nt = 0; nt < 4; nt++) {
                int col = s * 128 + wn * 32 + nt * 8 + (lane & 3) * 2;
                float* q0 = sP + (size_t)(r + 1) * PSTR + col;
                float* q1 = sP + (size_t)(r + 9) * PSTR + col;
                *reinterpret_cast<float2*>(q0) = make_float2(C[mt][nt][0], C[mt][nt][1]);
                *reinterpret_cast<float2*>(q1) = make_float2(C[mt][nt][2], C[mt][nt][3]);
            }
        }
    }
    __syncthreads();

    // ---- 4-way scan: thread (u, q) scans rows q*16+1 .. q*16+16 ----
    float* sMaps = reinterpret_cast<float*>(smem + OFF_MAPS);
    {
        const int u = tid & 63;
        const int q = tid >> 6;
        const int r0 = q * 16;

        float prev[10];
#pragma unroll
        for (int l = 0; l < 10; l++) prev[l] = sP[(size_t)r0 * PSTR + l * 64 + u];

        float e1=0.f,e3=0.f,e4=0.f,e43=0.f,e6=0.f,e7=0.f,e76=0.f,e8=0.f,e87=0.f,e876=0.f;
        float S2=0.f,S5=0.f,S9=0.f,W21=0.f,W54=0.f,W543=0.f,W98=0.f,W987=0.f,W9876=0.f,y0=0.f;

#pragma unroll 4
        for (int i = 1; i <= 16; i++) {
            const float* p = sP + (size_t)(r0 + i) * PSTR + u;
            float m[10];
#pragma unroll
            for (int l = 0; l < 10; l++) {
                float v = p[l * 64];
                m[l] = v - prev[l];
                prev[l] = v;
            }
            // All RHS use pre-update (exclusive) values.
            y0   += m[0];
            W21   = fmaf(m[2], e1,   W21);   S2 += m[2];
            W54   = fmaf(m[5], e4,   W54);
            W543  = fmaf(m[5], e43,  W543);  S5 += m[5];
            W98   = fmaf(m[9], e8,   W98);
            W987  = fmaf(m[9], e87,  W987);
            W9876 = fmaf(m[9], e876, W9876); S9 += m[9];
            e43   = fmaf(m[4], e3,   e43);
            e876  = fmaf(m[8], e76,  e876);
            e87   = fmaf(m[8], e7,   e87);
            e76   = fmaf(m[7], e6,   e76);
            e1 += m[1]; e3 += m[3]; e4 += m[4];
            e6 += m[6]; e7 += m[7]; e8 += m[8];
        }

        float* mp = sMaps + (size_t)(q * 64 + u) * 17;
        mp[0]  = y0 + W21 + W543 + W9876;
        mp[1]  = S2;  mp[2]  = S5;  mp[3]  = S9;
        mp[4]  = W54; mp[5]  = W98; mp[6]  = W987;
        mp[7]  = e1;  mp[8]  = e3;  mp[9]  = e4;
        mp[10] = e43; mp[11] = e6;  mp[12] = e7;
        mp[13] = e76; mp[14] = e8;  mp[15] = e87;
        mp[16] = e876;
    }
    __syncthreads();

    // ---- Compose 4 sub-maps per chain, write g_W[chain][c][17] ----
    if (tid < 64) {
        const int u = tid;
        SigMap M[4];
#pragma unroll
        for (int q = 0; q < 4; q++) {
            const float* mp = sMaps + (size_t)(q * 64 + u) * 17;
            M[q].Y0  = mp[0];  M[q].S2  = mp[1];  M[q].S5  = mp[2];
            M[q].S9  = mp[3];  M[q].W54 = mp[4];  M[q].W98 = mp[5];
            M[q].W987= mp[6];  M[q].E1  = mp[7];  M[q].E3  = mp[8];
            M[q].E4  = mp[9];  M[q].E43 = mp[10]; M[q].E6  = mp[11];
            M[q].E7  = mp[12]; M[q].E76 = mp[13]; M[q].E8  = mp[14];
            M[q].E87 = mp[15]; M[q].E876= mp[16];
        }
        SigMap R = sig_compose(sig_compose(M[0], M[1]), sig_compose(M[2], M[3]));

        const int chain = b * 64 + u;
        float* wp = g_W + ((size_t)chain * NCH + c) * 17;
        wp[0]  = R.Y0;  wp[1]  = R.S2;  wp[2]  = R.S5;  wp[3]  = R.S9;
        wp[4]  = R.W54; wp[5]  = R.W98; wp[6]  = R.W987;
        wp[7]  = R.E1;  wp[8]  = R.E3;  wp[9]  = R.E4;  wp[10] = R.E43;
        wp[11] = R.E6;  wp[12] = R.E7;  wp[13] = R.E76;
        wp[14] = R.E8;  wp[15] = R.E87; wp[16] = R.E876;
    }
}

// ---------------- Combine: warp-tree composition over 32 chunks ----------------
__device__ __forceinline__ SigMap sig_shfl_down(const SigMap& m, int o) {
    SigMap r;
    r.Y0  = __shfl_down_sync(0xffffffffu, m.Y0,  o);
    r.S2  = __shfl_down_sync(0xffffffffu, m.S2,  o);
    r.S5  = __shfl_down_sync(0xffffffffu, m.S5,  o);
    r.S9  = __shfl_down_sync(0xffffffffu, m.S9,  o);
    r.W54 = __shfl_down_sync(0xffffffffu, m.W54, o);
    r.W98 = __shfl_down_sync(0xffffffffu, m.W98, o);
    r.W987= __shfl_down_sync(0xffffffffu, m.W987,o);
    r.E1  = __shfl_down_sync(0xffffffffu, m.E1,  o);
    r.E3  = __shfl_down_sync(0xffffffffu, m.E3,  o);
    r.E4  = __shfl_down_sync(0xffffffffu, m.E4,  o);
    r.E43 = __shfl_down_sync(0xffffffffu, m.E43, o);
    r.E6  = __shfl_down_sync(0xffffffffu, m.E6,  o);
    r.E7  = __shfl_down_sync(0xffffffffu, m.E7,  o);
    r.E76 = __shfl_down_sync(0xffffffffu, m.E76, o);
    r.E8  = __shfl_down_sync(0xffffffffu, m.E8,  o);
    r.E87 = __shfl_down_sync(0xffffffffu, m.E87, o);
    r.E876= __shfl_down_sync(0xffffffffu, m.E876,o);
    return r;
}

extern "C" __global__ void __launch_bounds__(256)
lrsig_combine(float* __restrict__ out)
{
    const int chain = blockIdx.x * 8 + (threadIdx.x >> 5);
    const int lane  = threadIdx.x & 31;

    const float* wp = g_W + ((size_t)chain * NCH + lane) * 17;
    SigMap M;
    M.Y0  = wp[0];  M.S2  = wp[1];  M.S5  = wp[2];  M.S9  = wp[3];
    M.W54 = wp[4];  M.W98 = wp[5];  M.W987= wp[6];
    M.E1  = wp[7];  M.E3  = wp[8];  M.E4  = wp[9];  M.E43 = wp[10];
    M.E6  = wp[11]; M.E7  = wp[12]; M.E76 = wp[13];
    M.E8  = wp[14]; M.E87 = wp[15]; M.E876= wp[16];

#pragma unroll
    for (int o = 1; o < 32; o <<= 1)
        M = sig_compose(M, sig_shfl_down(M, o));   // lane 0 exact after tree

    if (lane == 0) out[chain] = M.Y0;   // initial state zero -> Y = Y0
}

// ---------------- Launch ----------------
extern "C" void kernel_launch(void* const* d_in, const int* in_sizes, int n_in,
                              void* d_out, int out_size)
{
    const float* x    = (const float*)d_in[0];  // (32, 2048, 63) f32
    const float* kern = (const float*)d_in[1];  // (64, 10, 64)  f32

    cudaFuncSetAttribute(lrsig_fused, cudaFuncAttributeMaxDynamicSharedMemorySize,
                         SMEM_TOTAL);

    lrsig_fused<<<dim3(NCH, BB), 256, SMEM_TOTAL>>>(x, kern);
    lrsig_combine<<<NCHAIN / 8, 256>>>((float*)d_out);
}

// round 10
// speedup vs baseline: 3.9430x; 1.5146x over previous
#include <cuda_runtime.h>
#include <cuda_bf16.h>
#include <cstdint>
#include <cstddef>

// Problem constants
#define BB     32
#define TT     2048
#define FIN    63
#define FDIM   64
#define LUDIM  640
#define NCH    32      // chunks of 64 timesteps
#define TCH    64
#define NCHAIN 2048

// smem byte offsets (fused kernel)
#define XSTR   72      // X row stride (bf16 elems)
#define KSTR   136     // K row stride (bf16 elems), [f][j] layout (17 uint4/row)
#define PSTR   648     // sP row stride (floats)
#define OFF_XH 0
#define OFF_XL 9216            // 64*72*2
#define OFF_KH 18432
#define OFF_KL 35840           // +64*136*2 = 17408
#define OFF_SP 53248
#define SMEM_TOTAL (OFF_SP + 65 * PSTR * 4)   // 221728 B
// 8 sub-chunk SigMaps per chain staged over the K region (8*64*17*4 = 34816 B)
#define OFF_MAPS OFF_KH

// Precomputed bf16 hi/lo split of kernel, [f][lu]
__device__ __nv_bfloat16 g_KH[FDIM * LUDIM];
__device__ __nv_bfloat16 g_KL[FDIM * LUDIM];
// g_W layout: [chain][c][17]  (combine reads coalesced)
__device__ float g_W[(size_t)NCHAIN * NCH * 17];

// ---------------- PTX helpers ----------------
__device__ __forceinline__ uint32_t smem_u32(const void* p) {
    uint32_t a;
    asm("{ .reg .u64 t; cvta.to.shared.u64 t, %1; cvt.u32.u64 %0, t; }" : "=r"(a) : "l"(p));
    return a;
}
__device__ __forceinline__ void ldsm_x4(uint32_t& r0, uint32_t& r1, uint32_t& r2, uint32_t& r3,
                                        uint32_t addr) {
    asm volatile("ldmatrix.sync.aligned.m8n8.x4.shared.b16 {%0,%1,%2,%3}, [%4];"
                 : "=r"(r0), "=r"(r1), "=r"(r2), "=r"(r3) : "r"(addr));
}
__device__ __forceinline__ void ldsm_x4t(uint32_t& r0, uint32_t& r1, uint32_t& r2, uint32_t& r3,
                                         uint32_t addr) {
    asm volatile("ldmatrix.sync.aligned.m8n8.x4.trans.shared.b16 {%0,%1,%2,%3}, [%4];"
                 : "=r"(r0), "=r"(r1), "=r"(r2), "=r"(r3) : "r"(addr));
}
__device__ __forceinline__ void mma_bf16(float* c, const uint32_t* a, uint32_t b0, uint32_t b1) {
    asm volatile(
        "mma.sync.aligned.m16n8k16.row.col.f32.bf16.bf16.f32 "
        "{%0,%1,%2,%3}, {%4,%5,%6,%7}, {%8,%9}, {%0,%1,%2,%3};"
        : "+f"(c[0]), "+f"(c[1]), "+f"(c[2]), "+f"(c[3])
        : "r"(a[0]), "r"(a[1]), "r"(a[2]), "r"(a[3]), "r"(b0), "r"(b1));
}

// ---------------- Chen map: 17 coefficients ----------------
struct SigMap {
    float Y0,S2,S5,S9,W54,W98,W987,E1,E3,E4,E43,E6,E7,E76,E8,E87,E876;
};

// C = B after A (A covers earlier time)
__device__ __forceinline__ SigMap sig_compose(const SigMap& A, const SigMap& B) {
    SigMap C;
    C.E1   = A.E1 + B.E1;
    C.E3   = A.E3 + B.E3;
    C.E6   = A.E6 + B.E6;
    C.E4   = A.E4 + B.E4;
    C.E43  = A.E43 + A.E3 * B.E4 + B.E43;
    C.E7   = A.E7 + B.E7;
    C.E76  = A.E76 + A.E6 * B.E7 + B.E76;
    C.E8   = A.E8 + B.E8;
    C.E87  = A.E87 + A.E7 * B.E8 + B.E87;
    C.E876 = A.E876 + A.E76 * B.E8 + A.E6 * B.E87 + B.E876;
    C.S2   = A.S2 + B.S2;
    C.S5   = A.S5 + B.S5;
    C.S9   = A.S9 + B.S9;
    C.W54  = A.W54 + A.E4 * B.S5 + B.W54;
    C.W98  = A.W98 + A.E8 * B.S9 + B.W98;
    C.W987 = A.W987 + A.E87 * B.S9 + A.E7 * B.W98 + B.W987;
    C.Y0   = A.Y0 + B.Y0 + A.E1 * B.S2 + A.E43 * B.S5 + A.E3 * B.W54
           + A.E876 * B.S9 + A.E76 * B.W98 + A.E6 * B.W987;
    return C;
}

__device__ __forceinline__ SigMap sig_load_smem(const float* mp) {
    SigMap m;
    m.Y0  = mp[0];  m.S2  = mp[1];  m.S5  = mp[2];  m.S9  = mp[3];
    m.W54 = mp[4];  m.W98 = mp[5];  m.W987= mp[6];
    m.E1  = mp[7];  m.E3  = mp[8];  m.E4  = mp[9];  m.E43 = mp[10];
    m.E6  = mp[11]; m.E7  = mp[12]; m.E76 = mp[13];
    m.E8  = mp[14]; m.E87 = mp[15]; m.E876= mp[16];
    return m;
}

// ---------------- Prep: K -> bf16 hi/lo in gmem (once per call) ----------------
extern "C" __global__ void __launch_bounds__(256)
lrsig_prep(const float* __restrict__ kern)
{
    int i = blockIdx.x * 256 + threadIdx.x;
    if (i < FDIM * LUDIM) {
        float v = kern[i];
        __nv_bfloat16 hi = __float2bfloat16(v);
        g_KH[i] = hi;
        g_KL[i] = __float2bfloat16(v - __bfloat162float(hi));
    }
}

// ---------------- Fused kernel: GEMM tile in smem + 8-way chunk scan ----------------
// Grid (NCH, BB) = (32, 32), 512 threads, 1 CTA/SM.
// 16 warps: wt = w&3 (16-row t quarter), wn = w>>2 (32-col lu quarter of stage).
extern "C" __global__ void __launch_bounds__(512, 1)
lrsig_fused(const float* __restrict__ x, const float* __restrict__ kern)
{
    extern __shared__ char smem[];
    float* sP = reinterpret_cast<float*>(smem + OFF_SP);
    const uint32_t sb = smem_u32(smem);

    const int tid  = threadIdx.x;
    const int lane = tid & 31;
    const int w    = tid >> 5;
    const int wt   = w & 3;
    const int wn   = w >> 2;
    const int c    = blockIdx.x;
    const int b    = blockIdx.y;
    const int t0   = c * TCH;

    // ---- X tile (hi/lo bf16 split), [t][f], stride 72 ----
    for (int e = tid; e < TCH * FDIM; e += 512) {
        int tl = e >> 6, f = e & 63;
        int t = t0 + tl;
        float v;
        if (f < FIN) v = x[((size_t)b * TT + t) * FIN + f];
        else         v = (float)t * (2.0f / 2047.0f) - 1.0f;
        __nv_bfloat16 hi = __float2bfloat16(v);
        __nv_bfloat16 lo = __float2bfloat16(v - __bfloat162float(hi));
        int off = (tl * XSTR + f) * 2;
        *reinterpret_cast<__nv_bfloat16*>(smem + OFF_XH + off) = hi;
        *reinterpret_cast<__nv_bfloat16*>(smem + OFF_XL + off) = lo;
    }

    // ---- Prev row: sP[0][j] = P[max(t0-1,0)][j], exact fp32 ----
    {
        const int tp = (c == 0) ? 0 : (t0 - 1);
        const float* xr = x + ((size_t)b * TT + tp) * FIN;
        const float tfeat = (float)tp * (2.0f / 2047.0f) - 1.0f;
        for (int j = tid; j < LUDIM; j += 512) {
            float acc = tfeat * kern[63 * LUDIM + j];
            for (int f = 0; f < FIN; f++)
                acc = fmaf(xr[f], kern[f * LUDIM + j], acc);
            sP[j] = acc;
        }
    }
    __syncthreads();

    // ---- Preload A fragments once (held across all 5 stages; 32 regs) ----
    const uint32_t a_off = (uint32_t)((lane & 15) * XSTR + ((lane >> 4) << 3)) * 2;
    uint32_t Ah[4][4], Al[4][4];
#pragma unroll
    for (int ks = 0; ks < 4; ks++) {
        uint32_t ra = (uint32_t)(wt * 16 * XSTR + ks * 16) * 2 + a_off;
        ldsm_x4(Ah[ks][0], Ah[ks][1], Ah[ks][2], Ah[ks][3], sb + OFF_XH + ra);
        ldsm_x4(Al[ks][0], Al[ks][1], Al[ks][2], Al[ks][3], sb + OFF_XL + ra);
    }

    const uint32_t b_off = (uint32_t)((((lane >> 3) & 1) * 8 + (lane & 7)) * KSTR
                                      + ((lane >> 4) << 3)) * 2;

    // ---- Stage loop: 5 stages of 128 lu ----
    for (int s = 0; s < 5; s++) {
        __syncthreads();   // prior stage's ldsm/scan reads complete before refill
        // K stage fill: straight uint4 copies of precomputed bf16 (2 per thread)
        {
            const uint4* srcH = reinterpret_cast<const uint4*>(g_KH);
            const uint4* srcL = reinterpret_cast<const uint4*>(g_KL);
            uint4* dstH = reinterpret_cast<uint4*>(smem + OFF_KH);
            uint4* dstL = reinterpret_cast<uint4*>(smem + OFF_KL);
            for (int e = tid; e < FDIM * 16; e += 512) {   // 64 f-rows x 16 uint4
                int f = e >> 4, v = e & 15;
                dstH[f * 17 + v] = srcH[f * 80 + s * 16 + v];
                dstL[f * 17 + v] = srcL[f * 80 + s * 16 + v];
            }
        }
        __syncthreads();

        float C[4][4];
#pragma unroll
        for (int nt = 0; nt < 4; nt++)
#pragma unroll
            for (int i = 0; i < 4; i++) C[nt][i] = 0.0f;

#pragma unroll
        for (int ks = 0; ks < 4; ks++)
#pragma unroll
            for (int q = 0; q < 2; q++) {
                uint32_t rb = (uint32_t)(ks * 16 * KSTR + (wn * 32 + q * 16)) * 2 + b_off;
                uint32_t Bh[4], Bl[4];
                ldsm_x4t(Bh[0], Bh[1], Bh[2], Bh[3], sb + OFF_KH + rb);
                ldsm_x4t(Bl[0], Bl[1], Bl[2], Bl[3], sb + OFF_KL + rb);
#pragma unroll
                for (int p = 0; p < 2; p++) {
                    float* cc = C[q * 2 + p];
                    mma_bf16(cc, Ah[ks], Bh[p * 2], Bh[p * 2 + 1]);
                    mma_bf16(cc, Al[ks], Bh[p * 2], Bh[p * 2 + 1]);
                    mma_bf16(cc, Ah[ks], Bl[p * 2], Bl[p * 2 + 1]);
                }
            }

        // Epilogue into sP rows 1..64 (row = t-local + 1)
        {
            int r = wt * 16 + (lane >> 2);
#pragma unroll
            for (int nt = 0; nt < 4; nt++) {
                int col = s * 128 + wn * 32 + nt * 8 + (lane & 3) * 2;
                float* q0 = sP + (size_t)(r + 1) * PSTR + col;
                float* q1 = sP + (size_t)(r + 9) * PSTR + col;
                *reinterpret_cast<float2*>(q0) = make_float2(C[nt][0], C[nt][1]);
                *reinterpret_cast<float2*>(q1) = make_float2(C[nt][2], C[nt][3]);
            }
        }
    }
    __syncthreads();

    // ---- 8-way scan: thread (u, q) scans rows q*8+1 .. q*8+8 ----
    float* sMaps = reinterpret_cast<float*>(smem + OFF_MAPS);
    {
        const int u = tid & 63;
        const int q = tid >> 6;        // 0..7
        const int r0 = q * 8;

        float prev[10];
#pragma unroll
        for (int l = 0; l < 10; l++) prev[l] = sP[(size_t)r0 * PSTR + l * 64 + u];

        float e1=0.f,e3=0.f,e4=0.f,e43=0.f,e6=0.f,e7=0.f,e76=0.f,e8=0.f,e87=0.f,e876=0.f;
        float S2=0.f,S5=0.f,S9=0.f,W21=0.f,W54=0.f,W543=0.f,W98=0.f,W987=0.f,W9876=0.f,y0=0.f;

#pragma unroll
        for (int i = 1; i <= 8; i++) {
            const float* p = sP + (size_t)(r0 + i) * PSTR + u;
            float m[10];
#pragma unroll
            for (int l = 0; l < 10; l++) {
                float v = p[l * 64];
                m[l] = v - prev[l];
                prev[l] = v;
            }
            // All RHS use pre-update (exclusive) values.
            y0   += m[0];
            W21   = fmaf(m[2], e1,   W21);   S2 += m[2];
            W54   = fmaf(m[5], e4,   W54);
            W543  = fmaf(m[5], e43,  W543);  S5 += m[5];
            W98   = fmaf(m[9], e8,   W98);
            W987  = fmaf(m[9], e87,  W987);
            W9876 = fmaf(m[9], e876, W9876); S9 += m[9];
            e43   = fmaf(m[4], e3,   e43);
            e876  = fmaf(m[8], e76,  e876);
            e87   = fmaf(m[8], e7,   e87);
            e76   = fmaf(m[7], e6,   e76);
            e1 += m[1]; e3 += m[3]; e4 += m[4];
            e6 += m[6]; e7 += m[7]; e8 += m[8];
        }

        float* mp = sMaps + (size_t)(q * 64 + u) * 17;
        mp[0]  = y0 + W21 + W543 + W9876;
        mp[1]  = S2;  mp[2]  = S5;  mp[3]  = S9;
        mp[4]  = W54; mp[5]  = W98; mp[6]  = W987;
        mp[7]  = e1;  mp[8]  = e3;  mp[9]  = e4;
        mp[10] = e43; mp[11] = e6;  mp[12] = e7;
        mp[13] = e76; mp[14] = e8;  mp[15] = e87;
        mp[16] = e876;
    }
    __syncthreads();

    // ---- Compose 8 sub-maps per chain, write g_W[chain][c][17] ----
    if (tid < 64) {
        const int u = tid;
        SigMap R = sig_load_smem(sMaps + (size_t)u * 17);
#pragma unroll
        for (int q = 1; q < 8; q++)
            R = sig_compose(R, sig_load_smem(sMaps + (size_t)(q * 64 + u) * 17));

        const int chain = b * 64 + u;
        float* wp = g_W + ((size_t)chain * NCH + c) * 17;
        wp[0]  = R.Y0;  wp[1]  = R.S2;  wp[2]  = R.S5;  wp[3]  = R.S9;
        wp[4]  = R.W54; wp[5]  = R.W98; wp[6]  = R.W987;
        wp[7]  = R.E1;  wp[8]  = R.E3;  wp[9]  = R.E4;  wp[10] = R.E43;
        wp[11] = R.E6;  wp[12] = R.E7;  wp[13] = R.E76;
        wp[14] = R.E8;  wp[15] = R.E87; wp[16] = R.E876;
    }
}

// ---------------- Combine: warp-tree composition over 32 chunks ----------------
__device__ __forceinline__ SigMap sig_shfl_down(const SigMap& m, int o) {
    SigMap r;
    r.Y0  = __shfl_down_sync(0xffffffffu, m.Y0,  o);
    r.S2  = __shfl_down_sync(0xffffffffu, m.S2,  o);
    r.S5  = __shfl_down_sync(0xffffffffu, m.S5,  o);
    r.S9  = __shfl_down_sync(0xffffffffu, m.S9,  o);
    r.W54 = __shfl_down_sync(0xffffffffu, m.W54, o);
    r.W98 = __shfl_down_sync(0xffffffffu, m.W98, o);
    r.W987= __shfl_down_sync(0xffffffffu, m.W987,o);
    r.E1  = __shfl_down_sync(0xffffffffu, m.E1,  o);
    r.E3  = __shfl_down_sync(0xffffffffu, m.E3,  o);
    r.E4  = __shfl_down_sync(0xffffffffu, m.E4,  o);
    r.E43 = __shfl_down_sync(0xffffffffu, m.E43, o);
    r.E6  = __shfl_down_sync(0xffffffffu, m.E6,  o);
    r.E7  = __shfl_down_sync(0xffffffffu, m.E7,  o);
    r.E76 = __shfl_down_sync(0xffffffffu, m.E76, o);
    r.E8  = __shfl_down_sync(0xffffffffu, m.E8,  o);
    r.E87 = __shfl_down_sync(0xffffffffu, m.E87, o);
    r.E876= __shfl_down_sync(0xffffffffu, m.E876,o);
    return r;
}

extern "C" __global__ void __launch_bounds__(256)
lrsig_combine(float* __restrict__ out)
{
    const int chain = blockIdx.x * 8 + (threadIdx.x >> 5);
    const int lane  = threadIdx.x & 31;

    const float* wp = g_W + ((size_t)chain * NCH + lane) * 17;
    SigMap M = sig_load_smem(wp);   // coalesced-ish: 68B per lane, contiguous warp span

#pragma unroll
    for (int o = 1; o < 32; o <<= 1)
        M = sig_compose(M, sig_shfl_down(M, o));   // lane 0 exact after tree

    if (lane == 0) out[chain] = M.Y0;   // initial state zero -> Y = Y0
}

// ---------------- Launch ----------------
extern "C" void kernel_launch(void* const* d_in, const int* in_sizes, int n_in,
                              void* d_out, int out_size)
{
    const float* x    = (const float*)d_in[0];  // (32, 2048, 63) f32
    const float* kern = (const float*)d_in[1];  // (64, 10, 64)  f32

    cudaFuncSetAttribute(lrsig_fused, cudaFuncAttributeMaxDynamicSharedMemorySize,
                         SMEM_TOTAL);

    lrsig_prep<<<(FDIM * LUDIM + 255) / 256, 256>>>(kern);
    lrsig_fused<<<dim3(NCH, BB), 512, SMEM_TOTAL>>>(x, kern);
    lrsig_combine<<<NCHAIN / 8, 256>>>((float*)d_out);
}